// round 15
// baseline (speedup 1.0000x reference)
#include <cuda_runtime.h>
#include <cuda_bf16.h>
#include <cstdint>
#include <math.h>

#define T_SEQ 512
#define NB    256
#define KIN   300
#define HID   256

typedef unsigned long long ull;

// ---------------- static scratch (no allocations allowed) ----------------
__device__ float g_xp[(size_t)T_SEQ * NB * HID];   // xp[t][b][h], 128 MB
__device__ float g_hT[NB * HID];                   // final hidden state

// ---------------- portable tensor-core helpers (sm_80+ mma.sync) ---------
__device__ __forceinline__ uint32_t smem_u32(const void* p) {
    uint32_t a;
    asm("{ .reg .u64 t; cvta.to.shared.u64 t, %1; cvt.u32.u64 %0, t; }" : "=r"(a) : "l"(p));
    return a;
}
__device__ __forceinline__ void ldsm4(uint32_t* r, uint32_t addr) {
    asm volatile("ldmatrix.sync.aligned.m8n8.x4.shared.b16 {%0,%1,%2,%3}, [%4];"
                 : "=r"(r[0]), "=r"(r[1]), "=r"(r[2]), "=r"(r[3]) : "r"(addr));
}
__device__ __forceinline__ void mma16816(float* c, const uint32_t* a,
                                         uint32_t b0, uint32_t b1) {
    asm volatile(
        "mma.sync.aligned.m16n8k16.row.col.f32.bf16.bf16.f32 "
        "{%0,%1,%2,%3}, {%4,%5,%6,%7}, {%8,%9}, {%0,%1,%2,%3};"
        : "+f"(c[0]), "+f"(c[1]), "+f"(c[2]), "+f"(c[3])
        : "r"(a[0]), "r"(a[1]), "r"(a[2]), "r"(a[3]), "r"(b0), "r"(b1));
}

// exact identity tanh(x) = 1 - 2/(exp(2x)+1); ex2/rcp approx are <=2ulp.
__device__ __forceinline__ float tanh_fast(float x) {
    float e, r;
    asm("ex2.approx.f32 %0, %1;" : "=f"(e) : "f"(x * 2.8853900817779268f));
    asm("rcp.approx.f32 %0, %1;" : "=f"(r) : "f"(e + 1.0f));
    return fmaf(-2.0f, r, 1.0f);
}

// =========================================================================
// Tensor-core GEMM, bf16 split precision (measured 192 us — unchanged).
// =========================================================================
#define AH_OFF 0
#define AL_OFF (16 * 1024)
#define WH_OFF (32 * 1024)
#define WL_OFF (48 * 1024)
#define GEMM_SMEM (64 * 1024)
#define NKCH 5

__device__ __forceinline__ void cvt_sts(float4 v, char* smem, uint32_t hi_off,
                                        uint32_t lo_off, uint32_t sw) {
    __nv_bfloat162 h01 = __float22bfloat162_rn(make_float2(v.x, v.y));
    __nv_bfloat162 h23 = __float22bfloat162_rn(make_float2(v.z, v.w));
    float2 f01 = __bfloat1622float2(h01);
    float2 f23 = __bfloat1622float2(h23);
    __nv_bfloat162 l01 = __float22bfloat162_rn(make_float2(v.x - f01.x, v.y - f01.y));
    __nv_bfloat162 l23 = __float22bfloat162_rn(make_float2(v.z - f23.x, v.w - f23.y));
    *(uint2*)(smem + hi_off + sw) = make_uint2(*(uint32_t*)&h01, *(uint32_t*)&h23);
    *(uint2*)(smem + lo_off + sw) = make_uint2(*(uint32_t*)&l01, *(uint32_t*)&l23);
}

__global__ __launch_bounds__(256, 2) void gemm_mma(
    const float* __restrict__ A, const float* __restrict__ W,
    const float* __restrict__ b_ih, const float* __restrict__ b_hh)
{
    extern __shared__ __align__(1024) char smem[];
    const uint32_t sbase = smem_u32(smem);
    const int tid  = threadIdx.x;
    const int lane = tid & 31;
    const int wid  = tid >> 5;
    const int wm   = wid & 3;
    const int wn   = wid >> 2;
    const int m0 = blockIdx.y * 128;
    const int n0 = blockIdx.x * 128;

    float acc[2][8][4];
#pragma unroll
    for (int i = 0; i < 2; ++i)
#pragma unroll
        for (int j = 0; j < 8; ++j)
#pragma unroll
            for (int r = 0; r < 4; ++r) acc[i][j][r] = 0.f;

    const int a_row = wm * 32 + ((lane >> 3) & 1) * 8 + (lane & 7);
    const int a_kb  = (lane >> 4) * 8;
    const int b_row = wn * 64 + (lane >> 4) * 8 + (lane & 7);
    const int b_kb  = ((lane >> 3) & 1) * 8;

    for (int c = 0; c < NKCH; ++c) {
        const int k0g = c * 64;
        if (c) __syncthreads();

#pragma unroll
        for (int j = 0; j < 8; ++j) {
            int idx = tid + 256 * j;
            int row = idx >> 4, f4 = idx & 15;
            int colc = f4 * 4, colg = k0g + colc;
            float4 v = make_float4(0.f, 0.f, 0.f, 0.f);
            if (colg < KIN) v = __ldg((const float4*)(A + (size_t)(m0 + row) * KIN + colg));
            uint32_t bo = row * 128 + colc * 2;
            cvt_sts(v, smem, AH_OFF, AL_OFF, bo ^ ((bo >> 3) & 0x70));
        }
#pragma unroll
        for (int j = 0; j < 8; ++j) {
            int idx = tid + 256 * j;
            int row = idx >> 4, f4 = idx & 15;
            int colc = f4 * 4, colg = k0g + colc;
            float4 v = make_float4(0.f, 0.f, 0.f, 0.f);
            if (colg < KIN) v = __ldg((const float4*)(W + (size_t)(n0 + row) * KIN + colg));
            uint32_t bo = row * 128 + colc * 2;
            cvt_sts(v, smem, WH_OFF, WL_OFF, bo ^ ((bo >> 3) & 0x70));
        }
        __syncthreads();

#pragma unroll
        for (int s = 0; s < 4; ++s) {
            const int k0 = s * 16;
            uint32_t aoA[2], aoB[4];
#pragma unroll
            for (int i = 0; i < 2; ++i) {
                uint32_t bo = (a_row + i * 16) * 128 + (a_kb + k0) * 2;
                aoA[i] = bo ^ ((bo >> 3) & 0x70);
            }
#pragma unroll
            for (int j2 = 0; j2 < 4; ++j2) {
                uint32_t bo = (b_row + j2 * 16) * 128 + (b_kb + k0) * 2;
                aoB[j2] = bo ^ ((bo >> 3) & 0x70);
            }
            uint32_t ah[2][4], bh[4][4];
#pragma unroll
            for (int i = 0; i < 2; ++i)  ldsm4(ah[i],  sbase + AH_OFF + aoA[i]);
#pragma unroll
            for (int j2 = 0; j2 < 4; ++j2) ldsm4(bh[j2], sbase + WH_OFF + aoB[j2]);
#pragma unroll
            for (int j2 = 0; j2 < 4; ++j2)
#pragma unroll
                for (int i = 0; i < 2; ++i) {
                    mma16816(acc[i][2 * j2],     ah[i], bh[j2][0], bh[j2][1]);
                    mma16816(acc[i][2 * j2 + 1], ah[i], bh[j2][2], bh[j2][3]);
                }
#pragma unroll
            for (int j2 = 0; j2 < 4; ++j2) {
                uint32_t bl[4];
                ldsm4(bl, sbase + WL_OFF + aoB[j2]);
#pragma unroll
                for (int i = 0; i < 2; ++i) {
                    mma16816(acc[i][2 * j2],     ah[i], bl[0], bl[1]);
                    mma16816(acc[i][2 * j2 + 1], ah[i], bl[2], bl[3]);
                }
            }
#pragma unroll
            for (int i = 0; i < 2; ++i) {
                uint32_t al[4];
                ldsm4(al, sbase + AL_OFF + aoA[i]);
#pragma unroll
                for (int j2 = 0; j2 < 4; ++j2) {
                    mma16816(acc[i][2 * j2],     al, bh[j2][0], bh[j2][1]);
                    mma16816(acc[i][2 * j2 + 1], al, bh[j2][2], bh[j2][3]);
                }
            }
        }
    }

    const int g = lane >> 2, tig = lane & 3;
#pragma unroll
    for (int j = 0; j < 8; ++j) {
        const int col = n0 + wn * 64 + j * 8 + 2 * tig;
        const float bb0 = __ldg(b_ih + col)     + __ldg(b_hh + col);
        const float bb1 = __ldg(b_ih + col + 1) + __ldg(b_hh + col + 1);
#pragma unroll
        for (int i = 0; i < 2; ++i) {
            const int row = m0 + wm * 32 + i * 16 + g;
            *(float2*)(g_xp + (size_t)row * HID + col) =
                make_float2(acc[i][j][0] + bb0, acc[i][j][1] + bb1);
            *(float2*)(g_xp + (size_t)(row + 8) * HID + col) =
                make_float2(acc[i][j][2] + bb0, acc[i][j][3] + bb1);
        }
    }
}

// =========================================================================
// Tensor-core recurrent scan: 32 CTAs x 256 threads, 8 batches per CTA.
//   Per step: z[256r x 8b] = Wh(bf16, in regs) x (hh + hl)^T  via HMMA.
//   4-way accumulator chain split per m-tile ({hh,hl} x {kt even,odd}):
//   chain depth 8 (was 32) -> dependency-latency no longer binds.
//   Warp w owns rows [32w, 32w+32): 128 persistent W-frag regs.
//   One __syncthreads per step.
// =========================================================================
#define BPC 8

__global__ __launch_bounds__(256, 1) void scan_mma(const float* __restrict__ W_hh)
{
    __shared__ __align__(128) char hbuf[16384];  // [hh: 2x4KB][hl: 2x4KB]
    const uint32_t sb = smem_u32(hbuf);
    const int tid  = threadIdx.x;
    const int lane = tid & 31;
    const int wid  = tid >> 5;
    const int g = lane >> 2, c = lane & 3;
    const int b0 = blockIdx.x * BPC;
    const int R  = wid * 32;

    // ---- persistent Wh fragments (bf16 of W_hh rows [R, R+32), all k) ----
    uint32_t aw[2][16][4];
#pragma unroll
    for (int mt = 0; mt < 2; ++mt)
#pragma unroll
        for (int kt = 0; kt < 16; ++kt) {
            const float* p0 = W_hh + (size_t)(R + mt * 16 + g) * HID + kt * 16 + 2 * c;
            const float* p1 = p0 + 8 * HID;
            float2 v00 = __ldg((const float2*)p0);
            float2 v10 = __ldg((const float2*)p1);
            float2 v01 = __ldg((const float2*)(p0 + 8));
            float2 v11 = __ldg((const float2*)(p1 + 8));
            __nv_bfloat162 q0 = __float22bfloat162_rn(v00);
            __nv_bfloat162 q1 = __float22bfloat162_rn(v10);
            __nv_bfloat162 q2 = __float22bfloat162_rn(v01);
            __nv_bfloat162 q3 = __float22bfloat162_rn(v11);
            aw[mt][kt][0] = *(uint32_t*)&q0;
            aw[mt][kt][1] = *(uint32_t*)&q1;
            aw[mt][kt][2] = *(uint32_t*)&q2;
            aw[mt][kt][3] = *(uint32_t*)&q3;
        }

    // zero h buffers (h = 0 at t = 0)
#pragma unroll
    for (int i = 0; i < 4; ++i)
        ((float4*)hbuf)[tid + 256 * i] = make_float4(0.f, 0.f, 0.f, 0.f);
    __syncthreads();

    // xp: value v -> row = R + (v>>2)*16 + g + ((v>>1)&1)*8, b = 2c + (v&1)
    const float* xpb = g_xp + (size_t)b0 * HID;
    float xpv[8];
#pragma unroll
    for (int v = 0; v < 8; ++v) {
        int row = R + (v >> 2) * 16 + g + ((v >> 1) & 1) * 8;
        int bl = 2 * c + (v & 1);
        xpv[v] = __ldg(xpb + (size_t)bl * HID + row);
    }

    // ldmatrix lane address components (b = lane&7, k-chunk = lane>>3)
    const uint32_t lrow = (uint32_t)(lane & 7) * 512;
    const uint32_t kcs  = (uint32_t)(lane >> 3) * 16;
    const uint32_t bms  = (uint32_t)(lane & 7) << 4;

    float vout[8];
    for (int t = 0; t < T_SEQ; ++t) {
        const uint32_t rbh = sb + (t & 1) * 4096;
        const uint32_t rbl = sb + 8192 + (t & 1) * 4096;

        // prefetch next step's xp (consumed next iteration)
        float xpn[8];
        {
            const float* xt = xpb + (size_t)((t + 1 < T_SEQ) ? t + 1 : 0) * NB * HID;
#pragma unroll
            for (int v = 0; v < 8; ++v) {
                int row = R + (v >> 2) * 16 + g + ((v >> 1) & 1) * 8;
                int bl = 2 * c + (v & 1);
                xpn[v] = __ldg(xt + (size_t)bl * HID + row);
            }
        }

        // 4 independent chains per m-tile: [hh/hl][kt2 parity]
        float acc[2][4][4];
#pragma unroll
        for (int i = 0; i < 2; ++i)
#pragma unroll
            for (int ch = 0; ch < 4; ++ch)
#pragma unroll
                for (int r = 0; r < 4; ++r) acc[i][ch][r] = 0.f;

#pragma unroll
        for (int kt2 = 0; kt2 < 8; ++kt2) {
            const uint32_t koff = lrow + ((((uint32_t)kt2 * 64) | kcs) ^ bms);
            const int par = kt2 & 1;
            uint32_t bhh[4], bhl[4];
            ldsm4(bhh, rbh + koff);
            ldsm4(bhl, rbl + koff);
            mma16816(acc[0][par],     aw[0][2 * kt2],     bhh[0], bhh[1]);
            mma16816(acc[1][par],     aw[1][2 * kt2],     bhh[0], bhh[1]);
            mma16816(acc[0][par],     aw[0][2 * kt2 + 1], bhh[2], bhh[3]);
            mma16816(acc[1][par],     aw[1][2 * kt2 + 1], bhh[2], bhh[3]);
            mma16816(acc[0][2 + par], aw[0][2 * kt2],     bhl[0], bhl[1]);
            mma16816(acc[1][2 + par], aw[1][2 * kt2],     bhl[0], bhl[1]);
            mma16816(acc[0][2 + par], aw[0][2 * kt2 + 1], bhl[2], bhl[3]);
            mma16816(acc[1][2 + par], aw[1][2 * kt2 + 1], bhl[2], bhl[3]);
        }

        // epilogue: combine chains -> tanh -> split bf16 -> swizzled store
        char* whh = hbuf + ((t + 1) & 1) * 4096;
        char* whl = hbuf + 8192 + ((t + 1) & 1) * 4096;
#pragma unroll
        for (int v = 0; v < 8; ++v) {
            const int i = v >> 2, r = v & 3;
            const float z = ((acc[i][0][r] + acc[i][1][r]) +
                             (acc[i][2][r] + acc[i][3][r])) + xpv[v];
            const float hv = tanh_fast(z);
            const int row = R + i * 16 + g + ((v >> 1) & 1) * 8;
            const int bl = 2 * c + (v & 1);
            __nv_bfloat16 hh = __float2bfloat16(hv);
            __nv_bfloat16 hl = __float2bfloat16(hv - __bfloat162float(hh));
            const uint32_t off = (uint32_t)bl * 512 + (((uint32_t)(2 * row)) ^ ((uint32_t)bl << 4));
            *(__nv_bfloat16*)(whh + off) = hh;
            *(__nv_bfloat16*)(whl + off) = hl;
            vout[v] = hv;
        }
#pragma unroll
        for (int v = 0; v < 8; ++v) xpv[v] = xpn[v];
        __syncthreads();
    }

#pragma unroll
    for (int v = 0; v < 8; ++v) {
        const int row = R + (v >> 2) * 16 + g + ((v >> 1) & 1) * 8;
        const int bl = 2 * c + (v & 1);
        g_hT[(size_t)(b0 + bl) * HID + row] = vout[v];
    }
}

// =========================================================================
// Head: logits = hT @ W_fc^T + b_fc; out = log_softmax(logits)
// =========================================================================
__global__ void head_kernel(const float* __restrict__ W_fc,
                            const float* __restrict__ b_fc,
                            float* __restrict__ out)
{
    const int b = blockIdx.x, tid = threadIdx.x;
    float s0 = 0.f, s1 = 0.f;
    for (int h = tid; h < HID; h += 32) {
        float hv = g_hT[b * HID + h];
        s0 += hv * __ldg(W_fc + h);
        s1 += hv * __ldg(W_fc + HID + h);
    }
#pragma unroll
    for (int off = 16; off; off >>= 1) {
        s0 += __shfl_xor_sync(0xffffffffu, s0, off);
        s1 += __shfl_xor_sync(0xffffffffu, s1, off);
    }
    if (tid == 0) {
        float l0 = s0 + __ldg(b_fc), l1 = s1 + __ldg(b_fc + 1);
        float m = fmaxf(l0, l1);
        float lse = m + logf(expf(l0 - m) + expf(l1 - m));
        out[2 * b]     = l0 - lse;
        out[2 * b + 1] = l1 - lse;
    }
}

// =========================================================================
extern "C" void kernel_launch(void* const* d_in, const int* in_sizes, int n_in,
                              void* d_out, int out_size)
{
    const float* x    = (const float*)d_in[0];
    const float* W_ih = (const float*)d_in[1];
    const float* W_hh = (const float*)d_in[2];
    const float* b_ih = (const float*)d_in[3];
    const float* b_hh = (const float*)d_in[4];
    const float* W_fc = (const float*)d_in[5];
    const float* b_fc = (const float*)d_in[6];
    float* out = (float*)d_out;

    cudaFuncSetAttribute(gemm_mma,
                         cudaFuncAttributeMaxDynamicSharedMemorySize, GEMM_SMEM);

    gemm_mma<<<dim3(2, 1024), 256, GEMM_SMEM>>>(x, W_ih, b_ih, b_hh);
    scan_mma<<<32, 256>>>(W_hh);
    head_kernel<<<256, 32>>>(W_fc, b_fc, out);
}

// round 16
// speedup vs baseline: 1.2435x; 1.2435x over previous
#include <cuda_runtime.h>
#include <cuda_bf16.h>
#include <cstdint>
#include <math.h>

#define T_SEQ 512
#define NB    256
#define KIN   300
#define HID   256

typedef unsigned long long ull;

// ---------------- static scratch (no allocations allowed) ----------------
__device__ float g_xp[(size_t)T_SEQ * NB * HID];   // xp[t][b][h], 128 MB
__device__ float g_hT[NB * HID];                   // final hidden state

// ---------------- portable tensor-core helpers (sm_80+ mma.sync) ---------
__device__ __forceinline__ uint32_t smem_u32(const void* p) {
    uint32_t a;
    asm("{ .reg .u64 t; cvta.to.shared.u64 t, %1; cvt.u32.u64 %0, t; }" : "=r"(a) : "l"(p));
    return a;
}
__device__ __forceinline__ void ldsm4(uint32_t* r, uint32_t addr) {
    asm volatile("ldmatrix.sync.aligned.m8n8.x4.shared.b16 {%0,%1,%2,%3}, [%4];"
                 : "=r"(r[0]), "=r"(r[1]), "=r"(r[2]), "=r"(r[3]) : "r"(addr));
}
__device__ __forceinline__ void mma16816(float* c, const uint32_t* a,
                                         uint32_t b0, uint32_t b1) {
    asm volatile(
        "mma.sync.aligned.m16n8k16.row.col.f32.bf16.bf16.f32 "
        "{%0,%1,%2,%3}, {%4,%5,%6,%7}, {%8,%9}, {%0,%1,%2,%3};"
        : "+f"(c[0]), "+f"(c[1]), "+f"(c[2]), "+f"(c[3])
        : "r"(a[0]), "r"(a[1]), "r"(a[2]), "r"(a[3]), "r"(b0), "r"(b1));
}

// exact identity tanh(x) = 1 - 2/(exp(2x)+1); ex2/rcp approx are <=2ulp.
__device__ __forceinline__ float tanh_fast(float x) {
    float e, r;
    asm("ex2.approx.f32 %0, %1;" : "=f"(e) : "f"(x * 2.8853900817779268f));
    asm("rcp.approx.f32 %0, %1;" : "=f"(r) : "f"(e + 1.0f));
    return fmaf(-2.0f, r, 1.0f);
}

// =========================================================================
// Tensor-core GEMM, bf16 split precision (measured 192 us — unchanged).
// =========================================================================
#define AH_OFF 0
#define AL_OFF (16 * 1024)
#define WH_OFF (32 * 1024)
#define WL_OFF (48 * 1024)
#define GEMM_SMEM (64 * 1024)
#define NKCH 5

__device__ __forceinline__ void cvt_sts(float4 v, char* smem, uint32_t hi_off,
                                        uint32_t lo_off, uint32_t sw) {
    __nv_bfloat162 h01 = __float22bfloat162_rn(make_float2(v.x, v.y));
    __nv_bfloat162 h23 = __float22bfloat162_rn(make_float2(v.z, v.w));
    float2 f01 = __bfloat1622float2(h01);
    float2 f23 = __bfloat1622float2(h23);
    __nv_bfloat162 l01 = __float22bfloat162_rn(make_float2(v.x - f01.x, v.y - f01.y));
    __nv_bfloat162 l23 = __float22bfloat162_rn(make_float2(v.z - f23.x, v.w - f23.y));
    *(uint2*)(smem + hi_off + sw) = make_uint2(*(uint32_t*)&h01, *(uint32_t*)&h23);
    *(uint2*)(smem + lo_off + sw) = make_uint2(*(uint32_t*)&l01, *(uint32_t*)&l23);
}

__global__ __launch_bounds__(256, 2) void gemm_mma(
    const float* __restrict__ A, const float* __restrict__ W,
    const float* __restrict__ b_ih, const float* __restrict__ b_hh)
{
    extern __shared__ __align__(1024) char smem[];
    const uint32_t sbase = smem_u32(smem);
    const int tid  = threadIdx.x;
    const int lane = tid & 31;
    const int wid  = tid >> 5;
    const int wm   = wid & 3;
    const int wn   = wid >> 2;
    const int m0 = blockIdx.y * 128;
    const int n0 = blockIdx.x * 128;

    float acc[2][8][4];
#pragma unroll
    for (int i = 0; i < 2; ++i)
#pragma unroll
        for (int j = 0; j < 8; ++j)
#pragma unroll
            for (int r = 0; r < 4; ++r) acc[i][j][r] = 0.f;

    const int a_row = wm * 32 + ((lane >> 3) & 1) * 8 + (lane & 7);
    const int a_kb  = (lane >> 4) * 8;
    const int b_row = wn * 64 + (lane >> 4) * 8 + (lane & 7);
    const int b_kb  = ((lane >> 3) & 1) * 8;

    for (int c = 0; c < NKCH; ++c) {
        const int k0g = c * 64;
        if (c) __syncthreads();

#pragma unroll
        for (int j = 0; j < 8; ++j) {
            int idx = tid + 256 * j;
            int row = idx >> 4, f4 = idx & 15;
            int colc = f4 * 4, colg = k0g + colc;
            float4 v = make_float4(0.f, 0.f, 0.f, 0.f);
            if (colg < KIN) v = __ldg((const float4*)(A + (size_t)(m0 + row) * KIN + colg));
            uint32_t bo = row * 128 + colc * 2;
            cvt_sts(v, smem, AH_OFF, AL_OFF, bo ^ ((bo >> 3) & 0x70));
        }
#pragma unroll
        for (int j = 0; j < 8; ++j) {
            int idx = tid + 256 * j;
            int row = idx >> 4, f4 = idx & 15;
            int colc = f4 * 4, colg = k0g + colc;
            float4 v = make_float4(0.f, 0.f, 0.f, 0.f);
            if (colg < KIN) v = __ldg((const float4*)(W + (size_t)(n0 + row) * KIN + colg));
            uint32_t bo = row * 128 + colc * 2;
            cvt_sts(v, smem, WH_OFF, WL_OFF, bo ^ ((bo >> 3) & 0x70));
        }
        __syncthreads();

#pragma unroll
        for (int s = 0; s < 4; ++s) {
            const int k0 = s * 16;
            uint32_t aoA[2], aoB[4];
#pragma unroll
            for (int i = 0; i < 2; ++i) {
                uint32_t bo = (a_row + i * 16) * 128 + (a_kb + k0) * 2;
                aoA[i] = bo ^ ((bo >> 3) & 0x70);
            }
#pragma unroll
            for (int j2 = 0; j2 < 4; ++j2) {
                uint32_t bo = (b_row + j2 * 16) * 128 + (b_kb + k0) * 2;
                aoB[j2] = bo ^ ((bo >> 3) & 0x70);
            }
            uint32_t ah[2][4], bh[4][4];
#pragma unroll
            for (int i = 0; i < 2; ++i)  ldsm4(ah[i],  sbase + AH_OFF + aoA[i]);
#pragma unroll
            for (int j2 = 0; j2 < 4; ++j2) ldsm4(bh[j2], sbase + WH_OFF + aoB[j2]);
#pragma unroll
            for (int j2 = 0; j2 < 4; ++j2)
#pragma unroll
                for (int i = 0; i < 2; ++i) {
                    mma16816(acc[i][2 * j2],     ah[i], bh[j2][0], bh[j2][1]);
                    mma16816(acc[i][2 * j2 + 1], ah[i], bh[j2][2], bh[j2][3]);
                }
#pragma unroll
            for (int j2 = 0; j2 < 4; ++j2) {
                uint32_t bl[4];
                ldsm4(bl, sbase + WL_OFF + aoB[j2]);
#pragma unroll
                for (int i = 0; i < 2; ++i) {
                    mma16816(acc[i][2 * j2],     ah[i], bl[0], bl[1]);
                    mma16816(acc[i][2 * j2 + 1], ah[i], bl[2], bl[3]);
                }
            }
#pragma unroll
            for (int i = 0; i < 2; ++i) {
                uint32_t al[4];
                ldsm4(al, sbase + AL_OFF + aoA[i]);
#pragma unroll
                for (int j2 = 0; j2 < 4; ++j2) {
                    mma16816(acc[i][2 * j2],     al, bh[j2][0], bh[j2][1]);
                    mma16816(acc[i][2 * j2 + 1], al, bh[j2][2], bh[j2][3]);
                }
            }
        }
    }

    const int g = lane >> 2, tig = lane & 3;
#pragma unroll
    for (int j = 0; j < 8; ++j) {
        const int col = n0 + wn * 64 + j * 8 + 2 * tig;
        const float bb0 = __ldg(b_ih + col)     + __ldg(b_hh + col);
        const float bb1 = __ldg(b_ih + col + 1) + __ldg(b_hh + col + 1);
#pragma unroll
        for (int i = 0; i < 2; ++i) {
            const int row = m0 + wm * 32 + i * 16 + g;
            *(float2*)(g_xp + (size_t)row * HID + col) =
                make_float2(acc[i][j][0] + bb0, acc[i][j][1] + bb1);
            *(float2*)(g_xp + (size_t)(row + 8) * HID + col) =
                make_float2(acc[i][j][2] + bb0, acc[i][j][3] + bb1);
        }
    }
}

// =========================================================================
// Tensor-core recurrent scan: 32 CTAs x 256 threads, 8 batches per CTA.
//   Per step: z[256r x 8b] = Wh(bf16, in regs) x h(bf16)^T via HMMA.
//   h stored as SINGLE bf16 (no lo-compensation): 8 ldsm + 16 HMMA per
//   warp-step (half of R13). Mild 2-way parity chain split (acc[2][2][4],
//   depth 8) stays inside the proven register budget (~175 regs).
//   One __syncthreads per step.
// =========================================================================
#define BPC 8

__global__ __launch_bounds__(256, 1) void scan_mma(const float* __restrict__ W_hh)
{
    __shared__ __align__(128) char hbuf[8192];   // [2 bufs][8 b][256 k] bf16
    const uint32_t sb = smem_u32(hbuf);
    const int tid  = threadIdx.x;
    const int lane = tid & 31;
    const int wid  = tid >> 5;
    const int g = lane >> 2, c = lane & 3;
    const int b0 = blockIdx.x * BPC;
    const int R  = wid * 32;

    // ---- persistent Wh fragments (bf16 of W_hh rows [R, R+32), all k) ----
    uint32_t aw[2][16][4];
#pragma unroll
    for (int mt = 0; mt < 2; ++mt)
#pragma unroll
        for (int kt = 0; kt < 16; ++kt) {
            const float* p0 = W_hh + (size_t)(R + mt * 16 + g) * HID + kt * 16 + 2 * c;
            const float* p1 = p0 + 8 * HID;
            float2 v00 = __ldg((const float2*)p0);
            float2 v10 = __ldg((const float2*)p1);
            float2 v01 = __ldg((const float2*)(p0 + 8));
            float2 v11 = __ldg((const float2*)(p1 + 8));
            __nv_bfloat162 q0 = __float22bfloat162_rn(v00);
            __nv_bfloat162 q1 = __float22bfloat162_rn(v10);
            __nv_bfloat162 q2 = __float22bfloat162_rn(v01);
            __nv_bfloat162 q3 = __float22bfloat162_rn(v11);
            aw[mt][kt][0] = *(uint32_t*)&q0;
            aw[mt][kt][1] = *(uint32_t*)&q1;
            aw[mt][kt][2] = *(uint32_t*)&q2;
            aw[mt][kt][3] = *(uint32_t*)&q3;
        }

    // zero h buffers (h = 0 at t = 0)
#pragma unroll
    for (int i = 0; i < 2; ++i)
        ((float4*)hbuf)[tid + 256 * i] = make_float4(0.f, 0.f, 0.f, 0.f);
    __syncthreads();

    // xp: value v -> row = R + (v>>2)*16 + g + ((v>>1)&1)*8, b = 2c + (v&1)
    const float* xpb = g_xp + (size_t)b0 * HID;
    float xpv[8];
#pragma unroll
    for (int v = 0; v < 8; ++v) {
        int row = R + (v >> 2) * 16 + g + ((v >> 1) & 1) * 8;
        int bl = 2 * c + (v & 1);
        xpv[v] = __ldg(xpb + (size_t)bl * HID + row);
    }

    // ldmatrix lane address components (b = lane&7, k-chunk = lane>>3)
    const uint32_t lrow = (uint32_t)(lane & 7) * 512;
    const uint32_t kcs  = (uint32_t)(lane >> 3) * 16;
    const uint32_t bms  = (uint32_t)(lane & 7) << 4;

    float vout[8];
    for (int t = 0; t < T_SEQ; ++t) {
        const uint32_t rbh = sb + (t & 1) * 4096;

        // prefetch next step's xp (consumed next iteration)
        float xpn[8];
        {
            const float* xt = xpb + (size_t)((t + 1 < T_SEQ) ? t + 1 : 0) * NB * HID;
#pragma unroll
            for (int v = 0; v < 8; ++v) {
                int row = R + (v >> 2) * 16 + g + ((v >> 1) & 1) * 8;
                int bl = 2 * c + (v & 1);
                xpn[v] = __ldg(xt + (size_t)bl * HID + row);
            }
        }

        // 2 chains per m-tile (kt2 parity), depth 8 each
        float acc[2][2][4];
#pragma unroll
        for (int i = 0; i < 2; ++i)
#pragma unroll
            for (int ch = 0; ch < 2; ++ch)
#pragma unroll
                for (int r = 0; r < 4; ++r) acc[i][ch][r] = 0.f;

#pragma unroll
        for (int kt2 = 0; kt2 < 8; ++kt2) {
            const uint32_t koff = lrow + ((((uint32_t)kt2 * 64) | kcs) ^ bms);
            const int par = kt2 & 1;
            uint32_t bhh[4];
            ldsm4(bhh, rbh + koff);
            mma16816(acc[0][par], aw[0][2 * kt2],     bhh[0], bhh[1]);
            mma16816(acc[1][par], aw[1][2 * kt2],     bhh[0], bhh[1]);
            mma16816(acc[0][par], aw[0][2 * kt2 + 1], bhh[2], bhh[3]);
            mma16816(acc[1][par], aw[1][2 * kt2 + 1], bhh[2], bhh[3]);
        }

        // epilogue: combine chains -> tanh -> bf16 -> swizzled h store
        char* whh = hbuf + ((t + 1) & 1) * 4096;
#pragma unroll
        for (int v = 0; v < 8; ++v) {
            const int i = v >> 2, r = v & 3;
            const float z = (acc[i][0][r] + acc[i][1][r]) + xpv[v];
            const float hv = tanh_fast(z);
            const int row = R + i * 16 + g + ((v >> 1) & 1) * 8;
            const int bl = 2 * c + (v & 1);
            __nv_bfloat16 hh = __float2bfloat16(hv);
            const uint32_t off = (uint32_t)bl * 512 + (((uint32_t)(2 * row)) ^ ((uint32_t)bl << 4));
            *(__nv_bfloat16*)(whh + off) = hh;
            vout[v] = hv;
        }
#pragma unroll
        for (int v = 0; v < 8; ++v) xpv[v] = xpn[v];
        __syncthreads();
    }

#pragma unroll
    for (int v = 0; v < 8; ++v) {
        const int row = R + (v >> 2) * 16 + g + ((v >> 1) & 1) * 8;
        const int bl = 2 * c + (v & 1);
        g_hT[(size_t)(b0 + bl) * HID + row] = vout[v];
    }
}

// =========================================================================
// Head: logits = hT @ W_fc^T + b_fc; out = log_softmax(logits)
// =========================================================================
__global__ void head_kernel(const float* __restrict__ W_fc,
                            const float* __restrict__ b_fc,
                            float* __restrict__ out)
{
    const int b = blockIdx.x, tid = threadIdx.x;
    float s0 = 0.f, s1 = 0.f;
    for (int h = tid; h < HID; h += 32) {
        float hv = g_hT[b * HID + h];
        s0 += hv * __ldg(W_fc + h);
        s1 += hv * __ldg(W_fc + HID + h);
    }
#pragma unroll
    for (int off = 16; off; off >>= 1) {
        s0 += __shfl_xor_sync(0xffffffffu, s0, off);
        s1 += __shfl_xor_sync(0xffffffffu, s1, off);
    }
    if (tid == 0) {
        float l0 = s0 + __ldg(b_fc), l1 = s1 + __ldg(b_fc + 1);
        float m = fmaxf(l0, l1);
        float lse = m + logf(expf(l0 - m) + expf(l1 - m));
        out[2 * b]     = l0 - lse;
        out[2 * b + 1] = l1 - lse;
    }
}

// =========================================================================
extern "C" void kernel_launch(void* const* d_in, const int* in_sizes, int n_in,
                              void* d_out, int out_size)
{
    const float* x    = (const float*)d_in[0];
    const float* W_ih = (const float*)d_in[1];
    const float* W_hh = (const float*)d_in[2];
    const float* b_ih = (const float*)d_in[3];
    const float* b_hh = (const float*)d_in[4];
    const float* W_fc = (const float*)d_in[5];
    const float* b_fc = (const float*)d_in[6];
    float* out = (float*)d_out;

    cudaFuncSetAttribute(gemm_mma,
                         cudaFuncAttributeMaxDynamicSharedMemorySize, GEMM_SMEM);

    gemm_mma<<<dim3(2, 1024), 256, GEMM_SMEM>>>(x, W_ih, b_ih, b_hh);
    scan_mma<<<32, 256>>>(W_hh);
    head_kernel<<<256, 32>>>(W_fc, b_fc, out);
}

// round 17
// speedup vs baseline: 1.4674x; 1.1800x over previous
#include <cuda_runtime.h>
#include <cuda_bf16.h>
#include <cstdint>
#include <math.h>

#define T_SEQ 512
#define NB    256
#define KIN   300
#define HID   256

typedef unsigned long long ull;

// ---------------- static scratch (no allocations allowed) ----------------
__device__ float g_xp[(size_t)T_SEQ * NB * HID];   // xp[t][b][h], 128 MB
__device__ float g_hT[NB * HID];                   // final hidden state

// ---------------- portable tensor-core helpers (sm_80+ mma.sync) ---------
__device__ __forceinline__ uint32_t smem_u32(const void* p) {
    uint32_t a;
    asm("{ .reg .u64 t; cvta.to.shared.u64 t, %1; cvt.u32.u64 %0, t; }" : "=r"(a) : "l"(p));
    return a;
}
__device__ __forceinline__ void ldsm4(uint32_t* r, uint32_t addr) {
    asm volatile("ldmatrix.sync.aligned.m8n8.x4.shared.b16 {%0,%1,%2,%3}, [%4];"
                 : "=r"(r[0]), "=r"(r[1]), "=r"(r[2]), "=r"(r[3]) : "r"(addr));
}
__device__ __forceinline__ void mma16816(float* c, const uint32_t* a,
                                         uint32_t b0, uint32_t b1) {
    asm volatile(
        "mma.sync.aligned.m16n8k16.row.col.f32.bf16.bf16.f32 "
        "{%0,%1,%2,%3}, {%4,%5,%6,%7}, {%8,%9}, {%0,%1,%2,%3};"
        : "+f"(c[0]), "+f"(c[1]), "+f"(c[2]), "+f"(c[3])
        : "r"(a[0]), "r"(a[1]), "r"(a[2]), "r"(a[3]), "r"(b0), "r"(b1));
}

// exact identity tanh(x) = 1 - 2/(exp(2x)+1); ex2/rcp approx are <=2ulp.
__device__ __forceinline__ float tanh_fast(float x) {
    float e, r;
    asm("ex2.approx.f32 %0, %1;" : "=f"(e) : "f"(x * 2.8853900817779268f));
    asm("rcp.approx.f32 %0, %1;" : "=f"(r) : "f"(e + 1.0f));
    return fmaf(-2.0f, r, 1.0f);
}

// =========================================================================
// Tensor-core GEMM, bf16 split precision (measured 192 us — unchanged).
// =========================================================================
#define AH_OFF 0
#define AL_OFF (16 * 1024)
#define WH_OFF (32 * 1024)
#define WL_OFF (48 * 1024)
#define GEMM_SMEM (64 * 1024)
#define NKCH 5

__device__ __forceinline__ void cvt_sts(float4 v, char* smem, uint32_t hi_off,
                                        uint32_t lo_off, uint32_t sw) {
    __nv_bfloat162 h01 = __float22bfloat162_rn(make_float2(v.x, v.y));
    __nv_bfloat162 h23 = __float22bfloat162_rn(make_float2(v.z, v.w));
    float2 f01 = __bfloat1622float2(h01);
    float2 f23 = __bfloat1622float2(h23);
    __nv_bfloat162 l01 = __float22bfloat162_rn(make_float2(v.x - f01.x, v.y - f01.y));
    __nv_bfloat162 l23 = __float22bfloat162_rn(make_float2(v.z - f23.x, v.w - f23.y));
    *(uint2*)(smem + hi_off + sw) = make_uint2(*(uint32_t*)&h01, *(uint32_t*)&h23);
    *(uint2*)(smem + lo_off + sw) = make_uint2(*(uint32_t*)&l01, *(uint32_t*)&l23);
}

__global__ __launch_bounds__(256, 2) void gemm_mma(
    const float* __restrict__ A, const float* __restrict__ W,
    const float* __restrict__ b_ih, const float* __restrict__ b_hh)
{
    extern __shared__ __align__(1024) char smem[];
    const uint32_t sbase = smem_u32(smem);
    const int tid  = threadIdx.x;
    const int lane = tid & 31;
    const int wid  = tid >> 5;
    const int wm   = wid & 3;
    const int wn   = wid >> 2;
    const int m0 = blockIdx.y * 128;
    const int n0 = blockIdx.x * 128;

    float acc[2][8][4];
#pragma unroll
    for (int i = 0; i < 2; ++i)
#pragma unroll
        for (int j = 0; j < 8; ++j)
#pragma unroll
            for (int r = 0; r < 4; ++r) acc[i][j][r] = 0.f;

    const int a_row = wm * 32 + ((lane >> 3) & 1) * 8 + (lane & 7);
    const int a_kb  = (lane >> 4) * 8;
    const int b_row = wn * 64 + (lane >> 4) * 8 + (lane & 7);
    const int b_kb  = ((lane >> 3) & 1) * 8;

    for (int c = 0; c < NKCH; ++c) {
        const int k0g = c * 64;
        if (c) __syncthreads();

#pragma unroll
        for (int j = 0; j < 8; ++j) {
            int idx = tid + 256 * j;
            int row = idx >> 4, f4 = idx & 15;
            int colc = f4 * 4, colg = k0g + colc;
            float4 v = make_float4(0.f, 0.f, 0.f, 0.f);
            if (colg < KIN) v = __ldg((const float4*)(A + (size_t)(m0 + row) * KIN + colg));
            uint32_t bo = row * 128 + colc * 2;
            cvt_sts(v, smem, AH_OFF, AL_OFF, bo ^ ((bo >> 3) & 0x70));
        }
#pragma unroll
        for (int j = 0; j < 8; ++j) {
            int idx = tid + 256 * j;
            int row = idx >> 4, f4 = idx & 15;
            int colc = f4 * 4, colg = k0g + colc;
            float4 v = make_float4(0.f, 0.f, 0.f, 0.f);
            if (colg < KIN) v = __ldg((const float4*)(W + (size_t)(n0 + row) * KIN + colg));
            uint32_t bo = row * 128 + colc * 2;
            cvt_sts(v, smem, WH_OFF, WL_OFF, bo ^ ((bo >> 3) & 0x70));
        }
        __syncthreads();

#pragma unroll
        for (int s = 0; s < 4; ++s) {
            const int k0 = s * 16;
            uint32_t aoA[2], aoB[4];
#pragma unroll
            for (int i = 0; i < 2; ++i) {
                uint32_t bo = (a_row + i * 16) * 128 + (a_kb + k0) * 2;
                aoA[i] = bo ^ ((bo >> 3) & 0x70);
            }
#pragma unroll
            for (int j2 = 0; j2 < 4; ++j2) {
                uint32_t bo = (b_row + j2 * 16) * 128 + (b_kb + k0) * 2;
                aoB[j2] = bo ^ ((bo >> 3) & 0x70);
            }
            uint32_t ah[2][4], bh[4][4];
#pragma unroll
            for (int i = 0; i < 2; ++i)  ldsm4(ah[i],  sbase + AH_OFF + aoA[i]);
#pragma unroll
            for (int j2 = 0; j2 < 4; ++j2) ldsm4(bh[j2], sbase + WH_OFF + aoB[j2]);
#pragma unroll
            for (int j2 = 0; j2 < 4; ++j2)
#pragma unroll
                for (int i = 0; i < 2; ++i) {
                    mma16816(acc[i][2 * j2],     ah[i], bh[j2][0], bh[j2][1]);
                    mma16816(acc[i][2 * j2 + 1], ah[i], bh[j2][2], bh[j2][3]);
                }
#pragma unroll
            for (int j2 = 0; j2 < 4; ++j2) {
                uint32_t bl[4];
                ldsm4(bl, sbase + WL_OFF + aoB[j2]);
#pragma unroll
                for (int i = 0; i < 2; ++i) {
                    mma16816(acc[i][2 * j2],     ah[i], bl[0], bl[1]);
                    mma16816(acc[i][2 * j2 + 1], ah[i], bl[2], bl[3]);
                }
            }
#pragma unroll
            for (int i = 0; i < 2; ++i) {
                uint32_t al[4];
                ldsm4(al, sbase + AL_OFF + aoA[i]);
#pragma unroll
                for (int j2 = 0; j2 < 4; ++j2) {
                    mma16816(acc[i][2 * j2],     al, bh[j2][0], bh[j2][1]);
                    mma16816(acc[i][2 * j2 + 1], al, bh[j2][2], bh[j2][3]);
                }
            }
        }
    }

    const int g = lane >> 2, tig = lane & 3;
#pragma unroll
    for (int j = 0; j < 8; ++j) {
        const int col = n0 + wn * 64 + j * 8 + 2 * tig;
        const float bb0 = __ldg(b_ih + col)     + __ldg(b_hh + col);
        const float bb1 = __ldg(b_ih + col + 1) + __ldg(b_hh + col + 1);
#pragma unroll
        for (int i = 0; i < 2; ++i) {
            const int row = m0 + wm * 32 + i * 16 + g;
            *(float2*)(g_xp + (size_t)row * HID + col) =
                make_float2(acc[i][j][0] + bb0, acc[i][j][1] + bb1);
            *(float2*)(g_xp + (size_t)(row + 8) * HID + col) =
                make_float2(acc[i][j][2] + bb0, acc[i][j][3] + bb1);
        }
    }
}

// =========================================================================
// Tensor-core recurrent scan: 32 CTAs x 512 threads (16 warps), 8 b/CTA.
//   Warp w owns rows [16w, 16w+16): aw = 16 kt x 4 = 64 persistent regs.
//   4 warps/SMSP for latency hiding; per-warp step = 8 ldsm + 16 HMMA.
//   xp prefetch depth 2 (ring) to cover DRAM latency across 2 steps.
//   h single bf16, XOR-swizzled; one __syncthreads per step.
// =========================================================================
#define BPC 8

__global__ __launch_bounds__(512, 1) void scan_mma(const float* __restrict__ W_hh)
{
    __shared__ __align__(128) char hbuf[8192];   // [2 bufs][8 b][256 k] bf16
    const uint32_t sb = smem_u32(hbuf);
    const int tid  = threadIdx.x;
    const int lane = tid & 31;
    const int wid  = tid >> 5;                   // 0..15
    const int g = lane >> 2, c = lane & 3;
    const int b0 = blockIdx.x * BPC;
    const int R  = wid * 16;                     // 16 rows per warp

    // ---- persistent Wh fragments (bf16 of W_hh rows [R, R+16), all k) ----
    uint32_t aw[16][4];
#pragma unroll
    for (int kt = 0; kt < 16; ++kt) {
        const float* p0 = W_hh + (size_t)(R + g) * HID + kt * 16 + 2 * c;
        const float* p1 = p0 + 8 * HID;
        float2 v00 = __ldg((const float2*)p0);
        float2 v10 = __ldg((const float2*)p1);
        float2 v01 = __ldg((const float2*)(p0 + 8));
        float2 v11 = __ldg((const float2*)(p1 + 8));
        __nv_bfloat162 q0 = __float22bfloat162_rn(v00);
        __nv_bfloat162 q1 = __float22bfloat162_rn(v10);
        __nv_bfloat162 q2 = __float22bfloat162_rn(v01);
        __nv_bfloat162 q3 = __float22bfloat162_rn(v11);
        aw[kt][0] = *(uint32_t*)&q0;
        aw[kt][1] = *(uint32_t*)&q1;
        aw[kt][2] = *(uint32_t*)&q2;
        aw[kt][3] = *(uint32_t*)&q3;
    }

    // zero h buffers (h = 0 at t = 0): 8192 B = 512 float4
    ((float4*)hbuf)[tid] = make_float4(0.f, 0.f, 0.f, 0.f);
    __syncthreads();

    // xp mapping: output r (0..3) -> row = R + g + (r>>1)*8, b = 2c + (r&1)
    const float* xpb = g_xp + (size_t)b0 * HID;
    float xpv[4], xpn[4];
#pragma unroll
    for (int r = 0; r < 4; ++r) {
        const int row = R + g + (r >> 1) * 8;
        const int bl = 2 * c + (r & 1);
        xpv[r] = __ldg(xpb + (size_t)bl * HID + row);
        xpn[r] = __ldg(xpb + (size_t)NB * HID + (size_t)bl * HID + row);
    }

    // ldmatrix lane address components (b = lane&7, k-chunk = lane>>3)
    const uint32_t lrow = (uint32_t)(lane & 7) * 512;
    const uint32_t kcs  = (uint32_t)(lane >> 3) * 16;
    const uint32_t bms  = (uint32_t)(lane & 7) << 4;

    float vout[4];
    for (int t = 0; t < T_SEQ; ++t) {
        const uint32_t rbh = sb + (t & 1) * 4096;

        // prefetch xp[t+2] (depth-2 ring; consumed two steps later)
        float xp2[4];
        {
            const int tp = (t + 2 < T_SEQ) ? t + 2 : 0;
            const float* xt = xpb + (size_t)tp * NB * HID;
#pragma unroll
            for (int r = 0; r < 4; ++r) {
                const int row = R + g + (r >> 1) * 8;
                const int bl = 2 * c + (r & 1);
                xp2[r] = __ldg(xt + (size_t)bl * HID + row);
            }
        }

        // 2 chains (kt2 parity), depth 8 each
        float acc[2][4];
#pragma unroll
        for (int ch = 0; ch < 2; ++ch)
#pragma unroll
            for (int r = 0; r < 4; ++r) acc[ch][r] = 0.f;

#pragma unroll
        for (int kt2 = 0; kt2 < 8; ++kt2) {
            const uint32_t koff = lrow + ((((uint32_t)kt2 * 64) | kcs) ^ bms);
            const int par = kt2 & 1;
            uint32_t bhh[4];
            ldsm4(bhh, rbh + koff);
            mma16816(acc[par], aw[2 * kt2],     bhh[0], bhh[1]);
            mma16816(acc[par], aw[2 * kt2 + 1], bhh[2], bhh[3]);
        }

        // epilogue: combine chains -> tanh -> bf16 -> swizzled h store
        char* whh = hbuf + ((t + 1) & 1) * 4096;
#pragma unroll
        for (int r = 0; r < 4; ++r) {
            const float z = (acc[0][r] + acc[1][r]) + xpv[r];
            const float hv = tanh_fast(z);
            const int row = R + g + (r >> 1) * 8;
            const int bl = 2 * c + (r & 1);
            __nv_bfloat16 hh = __float2bfloat16(hv);
            const uint32_t off = (uint32_t)bl * 512 + (((uint32_t)(2 * row)) ^ ((uint32_t)bl << 4));
            *(__nv_bfloat16*)(whh + off) = hh;
            vout[r] = hv;
        }
#pragma unroll
        for (int r = 0; r < 4; ++r) { xpv[r] = xpn[r]; xpn[r] = xp2[r]; }
        __syncthreads();
    }

#pragma unroll
    for (int r = 0; r < 4; ++r) {
        const int row = R + g + (r >> 1) * 8;
        const int bl = 2 * c + (r & 1);
        g_hT[(size_t)(b0 + bl) * HID + row] = vout[r];
    }
}

// =========================================================================
// Head: logits = hT @ W_fc^T + b_fc; out = log_softmax(logits)
// =========================================================================
__global__ void head_kernel(const float* __restrict__ W_fc,
                            const float* __restrict__ b_fc,
                            float* __restrict__ out)
{
    const int b = blockIdx.x, tid = threadIdx.x;
    float s0 = 0.f, s1 = 0.f;
    for (int h = tid; h < HID; h += 32) {
        float hv = g_hT[b * HID + h];
        s0 += hv * __ldg(W_fc + h);
        s1 += hv * __ldg(W_fc + HID + h);
    }
#pragma unroll
    for (int off = 16; off; off >>= 1) {
        s0 += __shfl_xor_sync(0xffffffffu, s0, off);
        s1 += __shfl_xor_sync(0xffffffffu, s1, off);
    }
    if (tid == 0) {
        float l0 = s0 + __ldg(b_fc), l1 = s1 + __ldg(b_fc + 1);
        float m = fmaxf(l0, l1);
        float lse = m + logf(expf(l0 - m) + expf(l1 - m));
        out[2 * b]     = l0 - lse;
        out[2 * b + 1] = l1 - lse;
    }
}

// =========================================================================
extern "C" void kernel_launch(void* const* d_in, const int* in_sizes, int n_in,
                              void* d_out, int out_size)
{
    const float* x    = (const float*)d_in[0];
    const float* W_ih = (const float*)d_in[1];
    const float* W_hh = (const float*)d_in[2];
    const float* b_ih = (const float*)d_in[3];
    const float* b_hh = (const float*)d_in[4];
    const float* W_fc = (const float*)d_in[5];
    const float* b_fc = (const float*)d_in[6];
    float* out = (float*)d_out;

    cudaFuncSetAttribute(gemm_mma,
                         cudaFuncAttributeMaxDynamicSharedMemorySize, GEMM_SMEM);

    gemm_mma<<<dim3(2, 1024), 256, GEMM_SMEM>>>(x, W_ih, b_ih, b_hh);
    scan_mma<<<32, 512>>>(W_hh);
    head_kernel<<<256, 32>>>(W_fc, b_fc, out);
}